// round 17
// baseline (speedup 1.0000x reference)
#include <cuda_runtime.h>
#include <cuda_fp16.h>
#include <cstdint>
#include <cstddef>

#define DEV __device__ __forceinline__

// ---------------- problem constants ----------------
static constexpr int BB = 32;
static constexpr int SEQ = 2048;
static constexpr int DD = 1024;    // K
static constexpr int SZ = 1024;    // SIZE

static constexpr int M_TILE = 128;
static constexpr int N_TILE = 128;            // 2 CTAs/SM
static constexpr int PASSES = SZ / N_TILE;    // 8
static constexpr int K_CHUNK = 64;            // halves of K per chunk
static constexpr int NCHUNK = DD / K_CHUNK;   // 16
static constexpr int TOTAL_CHUNKS = PASSES * NCHUNK;   // 128
static constexpr int THREADS = 128;           // 4 warps: 2m x 2n, warp tile 64x64
static constexpr int KPH = 72;                // halves per smem row (144 B; conflict-free)

// smem: 3-stage ring of (A|B) halves + partial buffer
static constexpr int A_HALVES = M_TILE * KPH;             // 9216
static constexpr int B_HALVES = N_TILE * KPH;             // 9216
static constexpr int STAGE_HALVES = A_HALVES + B_HALVES;  // 18432
static constexpr int NSTAGE = 3;
static constexpr int RING_BYTES = NSTAGE * STAGE_HALVES * 2;   // 110592
static constexpr int SMEM_BYTES = RING_BYTES + M_TILE * 4;     // 111104 -> 2 CTAs/SM

// prep kernel grid partition (WO convert + term2 only; X handled in fused)
static constexpr int NW4 = SZ * DD / 4;                // 262144
static constexpr int WBLK = NW4 / (256 * 4);           // 256 blocks, 4 uint4/thread
static constexpr int TBLK = (SZ / 8) * BB;             // 4096 term2 blocks
static constexpr int PREP_GRID = WBLK + TBLK;          // 4352

// scratch: fp16 copies + packed (v, term2) table
__device__ __half g_Xh[(size_t)BB * SEQ * DD];   // 128 MB (written by fused CTAs)
__device__ __half g_WOh[(size_t)SZ * DD];        // 2 MB
__device__ float2 g_vt2[BB * SZ];                // {v[n], term2[b][n]}

// ---------------- helpers ----------------
DEV uint32_t smem_u32(const void* p) {
    uint32_t a;
    asm("{ .reg .u64 t; cvta.to.shared.u64 t, %1; cvt.u32.u64 %0, t; }" : "=r"(a) : "l"(p));
    return a;
}
DEV void cp16(uint32_t s, const void* g) {
    asm volatile("cp.async.cg.shared.global [%0], [%1], 16;" :: "r"(s), "l"(g));
}
DEV void cp_commit() { asm volatile("cp.async.commit_group;" ::: "memory"); }
template <int N> DEV void cp_wait() { asm volatile("cp.async.wait_group %0;" :: "n"(N) : "memory"); }

DEV float tanh_fast(float x) {
    float y;
    asm("tanh.approx.f32 %0, %1;" : "=f"(y) : "f"(x));
    return y;
}

DEV void mma_f16(float* d, const uint32_t* a, const uint32_t* b) {
    asm volatile(
        "mma.sync.aligned.m16n8k16.row.col.f32.f16.f16.f32 "
        "{%0,%1,%2,%3}, {%4,%5,%6,%7}, {%8,%9}, {%0,%1,%2,%3};"
        : "+f"(d[0]), "+f"(d[1]), "+f"(d[2]), "+f"(d[3])
        : "r"(a[0]), "r"(a[1]), "r"(a[2]), "r"(a[3]), "r"(b[0]), "r"(b[1]));
}

DEV uint2 cvt4(float4 u) {
    __half2 h0 = __floats2half2_rn(u.x, u.y);
    __half2 h1 = __floats2half2_rn(u.z, u.w);
    uint2 o;
    o.x = *(uint32_t*)&h0;
    o.y = *(uint32_t*)&h1;
    return o;
}

// Stage chunk T (pass = T/16, kc = T%16) into ring slot `slot`. 128 threads.
DEV void stage_T(char* smem, int slot, int T, const __half* Xbase, int tid) {
    const int kc = T & (NCHUNK - 1);
    const int p = T >> 4;
    const __half* asrc = Xbase + kc * K_CHUNK;
    const __half* bsrc = g_WOh + (size_t)p * N_TILE * DD + kc * K_CHUNK;
    const uint32_t sa = smem_u32(smem) + (uint32_t)slot * STAGE_HALVES * 2u;
    const uint32_t sbB = sa + A_HALVES * 2u;
#pragma unroll
    for (int it = 0; it < 8; it++) {   // A: [128 x 64h] = 1024 cp16
        const int gidx = tid + it * THREADS;
        const int r = gidx >> 3, c = gidx & 7;
        cp16(sa + (uint32_t)(r * KPH * 2 + c * 16), asrc + (size_t)r * DD + c * 8);
    }
#pragma unroll
    for (int it = 0; it < 8; it++) {   // B: [128 x 64h] = 1024 cp16
        const int gidx = tid + it * THREADS;
        const int r = gidx >> 3, c = gidx & 7;
        cp16(sbB + (uint32_t)(r * KPH * 2 + c * 16), bsrc + (size_t)r * DD + c * 8);
    }
}

// ---------------- prep: WO->fp16 + term2+v pack ----------------
__global__ void prep_kernel(const float4* __restrict__ WO,
                            const float* __restrict__ WG, const float* __restrict__ g,
                            const float* __restrict__ v) {
    const int bx = blockIdx.x;
    const int tid = threadIdx.x;

    if (bx < WBLK) {
        // ---- WO fp32 -> fp16 : 4 uint4 per thread ----
        uint2* dst = (uint2*)g_WOh;
        const int base = bx * 1024 + tid;
#pragma unroll
        for (int it = 0; it < 4; it++) {
            const int i = base + it * 256;
            dst[i] = cvt4(__ldcs(&WO[i]));
        }
        return;
    }

    // ---- term2 = WG @ g, packed with v ----
    __shared__ float4 gs[256];
    const int tb = bx - WBLK;               // 0..4095
    const int nblk = tb & ((SZ / 8) - 1);   // 0..127
    const int b = tb >> 7;                  // 0..31
    gs[tid] = ((const float4*)(g + (size_t)b * DD))[tid];
    __syncthreads();
    const int w = tid >> 5, l = tid & 31;
    const int n = nblk * 8 + w;
    const float4* wg4 = (const float4*)(WG + (size_t)n * DD);
    float s = 0.f;
#pragma unroll
    for (int i = 0; i < 8; i++) {
        float4 a = wg4[l + 32 * i];
        float4 gg = gs[l + 32 * i];
        s += a.x * gg.x + a.y * gg.y + a.z * gg.z + a.w * gg.w;
    }
#pragma unroll
    for (int o = 16; o; o >>= 1) s += __shfl_xor_sync(0xFFFFFFFFu, s, o);
    if (l == 0) g_vt2[b * SZ + n] = make_float2(v[n], s);
}

// ---------------- fused: per-CTA X convert + GEMM(fp16 mma.sync) + tanh + v-dot ----------------
__global__ __launch_bounds__(THREADS, 2)
void fused_kernel(const float4* __restrict__ X, float* __restrict__ out) {
    extern __shared__ char smem[];
    const int tid = threadIdx.x;
    const int lane = tid & 31, wid = tid >> 5;
    const int wm = wid >> 1, wn = wid & 1;      // 2 x 2 warp grid; warp tile 64x64
    const int m0 = blockIdx.x * M_TILE;
    const int bidx = m0 >> 11;

    // ---- phase 0: convert THIS CTA's A tile fp32 -> fp16 into its g_Xh slice ----
    {
        const float4* xsrc = X + (size_t)m0 * (DD / 4);
        uint2* xdst = (uint2*)(g_Xh + (size_t)m0 * DD);
#pragma unroll 4
        for (int i = tid; i < M_TILE * DD / 4; i += THREADS)
            xdst[i] = cvt4(__ldcs(&xsrc[i]));
        asm volatile("membar.gl;" ::: "memory");   // STG visible to cp.async L2 reads
        __syncthreads();
    }

    float* part = (float*)(smem + RING_BYTES);
    for (int i = tid; i < M_TILE; i += THREADS) part[i] = 0.f;

    const __half* Xbase = g_Xh + (size_t)m0 * DD;
    const float4* vt4 = (const float4*)(g_vt2 + (size_t)bidx * SZ);

    float racc[8];
#pragma unroll
    for (int j = 0; j < 8; j++) racc[j] = 0.f;

    float acc[4][8][4];
#pragma unroll
    for (int mt = 0; mt < 4; mt++)
#pragma unroll
        for (int nt = 0; nt < 8; nt++)
#pragma unroll
            for (int q = 0; q < 4; q++) acc[mt][nt][q] = 0.f;

    const int ar = lane >> 2;   // fragment row
    const int ak = lane & 3;    // fragment k-pair

    // prologue: prefetch chunks 0 and 1
    stage_T(smem, 0, 0, Xbase, tid);
    cp_commit();
    stage_T(smem, 1, 1, Xbase, tid);
    cp_commit();

    int bufR = 0;   // slot holding chunk T
    int bufS = 2;   // slot to stage chunk T+2 into

#pragma unroll 1
    for (int T = 0; T < TOTAL_CHUNKS; T++) {
        cp_wait<1>();        // own copies of chunk T complete
        __syncthreads();     // chunk T visible to all; slot bufS reads drained

        if (T + 2 < TOTAL_CHUNKS) stage_T(smem, bufS, T + 2, Xbase, tid);
        cp_commit();         // keep group counts aligned

        const uint32_t* As = (const uint32_t*)(smem + (size_t)bufR * STAGE_HALVES * 2);
        const uint32_t* Bs = As + A_HALVES / 2;

#pragma unroll
        for (int k16 = 0; k16 < 4; k16++) {
            const int ko = k16 * 8;
            uint32_t a[4][4], b[8][2];
#pragma unroll
            for (int mt = 0; mt < 4; mt++) {
                const int r0 = (wm * 64 + mt * 16 + ar) * (KPH / 2) + ko + ak;
                a[mt][0] = As[r0];
                a[mt][1] = As[r0 + 8 * (KPH / 2)];
                a[mt][2] = As[r0 + 4];
                a[mt][3] = As[r0 + 8 * (KPH / 2) + 4];
            }
#pragma unroll
            for (int nt = 0; nt < 8; nt++) {
                const int nb = (wn * 64 + nt * 8 + ar) * (KPH / 2) + ko + ak;
                b[nt][0] = Bs[nb];
                b[nt][1] = Bs[nb + 4];
            }
#pragma unroll
            for (int mt = 0; mt < 4; mt++)
#pragma unroll
                for (int nt = 0; nt < 8; nt++)
                    mma_f16(acc[mt][nt], a[mt], b[nt]);
        }

        // ---- pass boundary: epilogue (registers + L2 table; no barrier) ----
        if ((T & (NCHUNK - 1)) == NCHUNK - 1) {
            const int p = T >> 4;
#pragma unroll
            for (int mt = 0; mt < 4; mt++) {
#pragma unroll
                for (int nt = 0; nt < 8; nt++) {
                    const int gn = p * N_TILE + wn * 64 + nt * 8 + 2 * ak;
                    const float4 w = __ldg(&vt4[gn >> 1]);   // {v0, t20, v1, t21}
                    racc[mt * 2] += w.x * tanh_fast(acc[mt][nt][0] + w.y)
                                  + w.z * tanh_fast(acc[mt][nt][1] + w.w);
                    racc[mt * 2 + 1] += w.x * tanh_fast(acc[mt][nt][2] + w.y)
                                      + w.z * tanh_fast(acc[mt][nt][3] + w.w);
                    acc[mt][nt][0] = 0.f; acc[mt][nt][1] = 0.f;
                    acc[mt][nt][2] = 0.f; acc[mt][nt][3] = 0.f;
                }
            }
        }

        bufR = (bufR == 2) ? 0 : bufR + 1;
        bufS = (bufS == 2) ? 0 : bufS + 1;
    }

    // reduce over the 4 lanes of each column group
#pragma unroll
    for (int j = 0; j < 8; j++) {
        racc[j] += __shfl_xor_sync(0xFFFFFFFFu, racc[j], 1);
        racc[j] += __shfl_xor_sync(0xFFFFFFFFu, racc[j], 2);
    }
    if (ak == 0) {
#pragma unroll
        for (int j = 0; j < 8; j++) {
            const int row = wm * 64 + (j >> 1) * 16 + ar + (j & 1) * 8;
            atomicAdd(&part[row], racc[j]);
        }
    }
    __syncthreads();
    if (tid < M_TILE) out[m0 + tid] = part[tid];
}

// ---------------- launch ----------------
extern "C" void kernel_launch(void* const* d_in, const int* in_sizes, int n_in,
                              void* d_out, int out_size) {
    const float* X  = (const float*)d_in[0];   // inputs [B,S,D]
    const float* g  = (const float*)d_in[1];   // g [B,D]
    const float* WO = (const float*)d_in[2];   // WO [SIZE,D]
    const float* WG = (const float*)d_in[3];   // WG [SIZE,D]
    const float* v  = (const float*)d_in[4];   // v [1,SIZE]
    float* out = (float*)d_out;

    cudaFuncSetAttribute(fused_kernel, cudaFuncAttributeMaxDynamicSharedMemorySize, SMEM_BYTES);

    prep_kernel<<<PREP_GRID, 256>>>((const float4*)WO, WG, g, v);
    fused_kernel<<<(BB * SEQ) / M_TILE, THREADS, SMEM_BYTES>>>((const float4*)X, out);
}